// round 4
// baseline (speedup 1.0000x reference)
#include <cuda_runtime.h>

// SparseScatter: y = y_base with 4096 active 16x16x32 tiles overwritten by
// transposed x blocks (x is [a, C, 16, 16] -> output NHWC).
//
// Shapes (fixed by reference setup):
//   x:       (4096, 32, 16, 16) fp32   = 33,554,432 elems
//   y_base:  (8, 512, 512, 32)  fp32   = 67,108,864 elems
//   indices: (4096, 3) int32 (n, yb, xb) = 12,288 elems
//   bh=bw=sh=sw=16, oh=ow=0
//
// Strategy: inverse map block_id -> active index (8192 ints, device scratch),
// then one CTA per 16x16x32 tile: float4 copy from y_base if inactive, else
// gather-transpose from x (4 scalar LDGs per float4 store; L1 absorbs the
// sector overfetch since each CTA reads exactly one 32KB x block).
// DRAM traffic = 512 MB total (write 256 + x 128 + inactive y_base 128),
// which is the floor for this op.

#define Bn   8
#define Hh   512
#define Ww   512
#define Cc   32
#define GH   32      // H/16
#define GW   32      // W/16
#define NBLK (Bn*GH*GW)   // 8192
#define NACT 4096

__device__ int g_map[NBLK];

__global__ void init_map_k() {
    int i = blockIdx.x * blockDim.x + threadIdx.x;
    if (i < NBLK) g_map[i] = -1;
}

__global__ void fill_map_k(const int* __restrict__ idx) {
    int a = blockIdx.x * blockDim.x + threadIdx.x;
    if (a < NACT) {
        int n  = idx[3*a + 0];
        int yb = idx[3*a + 1];
        int xb = idx[3*a + 2];
        g_map[(n * GH + yb) * GW + xb] = a;
    }
}

// One CTA per block tile (8192 CTAs). Tile = 16 rows x 16 cols x 32 ch
// = 2048 float4. 256 threads x 8 iterations.
__global__ void __launch_bounds__(256)
scatter_main_k(const float* __restrict__ x,
               const float4* __restrict__ yb4,
               float4* __restrict__ out4) {
    int bid = blockIdx.x;
    int a   = g_map[bid];

    int xb = bid & 31;
    int yb = (bid >> 5) & 31;
    int n  = bid >> 10;

    int t = threadIdx.x;

    // float4 index of tile start:
    //   (n*H*W + (yb*16)*W + xb*16) * (C/4)
    int rowbase0 = (n * Hh * Ww + (yb << 4) * Ww + (xb << 4)) * (Cc / 4);
    const int rowstride4 = Ww * (Cc / 4);   // 4096 float4 per output row

    if (a < 0) {
        // pass-through copy, fully coalesced float4; batch loads for MLP
        float4 v[8];
        int    o[8];
        #pragma unroll
        for (int k = 0; k < 8; k++) {
            int p   = (k << 8) + t;       // 0..2047
            int i   = p >> 7;             // row 0..15 (128 float4 per row)
            int rem = p & 127;            // float4 within row
            o[k] = rowbase0 + i * rowstride4 + rem;
            v[k] = yb4[o[k]];
        }
        #pragma unroll
        for (int k = 0; k < 8; k++) out4[o[k]] = v[k];
    } else {
        // transpose-gather from x block a: x[a][ch][i][j] -> out[...,i,j,ch]
        const float* xblk = x + (long)a * (Cc * 16 * 16);   // 8192 floats
        #pragma unroll
        for (int k = 0; k < 8; k++) {
            int p   = (k << 8) + t;
            int i   = p >> 7;
            int rem = p & 127;
            int j   = rem >> 3;           // col 0..15
            int ch  = (rem & 7) << 2;     // channel group base
            int pos = (i << 4) + j;       // i*16 + j
            float4 v;
            v.x = xblk[(ch + 0) * 256 + pos];
            v.y = xblk[(ch + 1) * 256 + pos];
            v.z = xblk[(ch + 2) * 256 + pos];
            v.w = xblk[(ch + 3) * 256 + pos];
            out4[rowbase0 + i * rowstride4 + rem] = v;
        }
    }
}

extern "C" void kernel_launch(void* const* d_in, const int* in_sizes, int n_in,
                              void* d_out, int out_size) {
    const float* x      = nullptr;
    const float* y_base = nullptr;
    const int*   idx    = nullptr;

    for (int i = 0; i < n_in; i++) {
        if (in_sizes[i] == 33554432)      x      = (const float*)d_in[i];
        else if (in_sizes[i] == 67108864) y_base = (const float*)d_in[i];
        else if (in_sizes[i] == 12288)    idx    = (const int*)d_in[i];
    }

    init_map_k<<<NBLK / 256, 256>>>();
    fill_map_k<<<NACT / 256, 256>>>(idx);
    scatter_main_k<<<NBLK, 256>>>(x, (const float4*)y_base, (float4*)d_out);
}

// round 5
// speedup vs baseline: 1.0214x; 1.0214x over previous
#include <cuda_runtime.h>

// SparseScatter: y = y_base with 4096 active 16x16x32 tiles overwritten by
// transposed x blocks (x is [a, C, 16, 16] -> output NHWC).
//
// R5: (1) SMEM-staged transpose for active tiles — coalesced x loads,
//     conflict-free 257-stride padded SMEM (both STS and LDS phases hit all
//     32 banks), removing the 32-lines-per-warp L1 wavefront storm of the
//     direct gather. (2) fused single-CTA map build (was 2 kernels ~8us).
//     (3) __ldcs/__stcs streaming hints: 512MB streamed, no L2 reuse.
//
// Shapes (fixed by reference setup):
//   x: (4096, 32, 16, 16) fp32; y_base: (8, 512, 512, 32) fp32;
//   indices: (4096,3) int32 (n, yb, xb); bh=bw=sh=sw=16, oh=ow=0.
// DRAM floor = write 256MB + read x 128MB + read inactive y_base 128MB = 512MB.

#define Bn   8
#define Hh   512
#define Ww   512
#define Cc   32
#define GH   32
#define GW   32
#define NBLK (Bn*GH*GW)   // 8192
#define NACT 4096

__device__ int g_map[NBLK];

// Single CTA, 1024 threads: clear map, sync, fill from indices.
__global__ void __launch_bounds__(1024)
build_map_k(const int* __restrict__ idx) {
    int t = threadIdx.x;
    #pragma unroll
    for (int k = 0; k < NBLK / 1024; k++)
        g_map[k * 1024 + t] = -1;
    __syncthreads();
    #pragma unroll
    for (int k = 0; k < NACT / 1024; k++) {
        int a  = k * 1024 + t;
        int n  = idx[3*a + 0];
        int yb = idx[3*a + 1];
        int xb = idx[3*a + 2];
        g_map[(n * GH + yb) * GW + xb] = a;
    }
}

// One CTA per 16x16x32 tile (8192 CTAs), 256 threads, 2048 float4 per tile.
__global__ void __launch_bounds__(256)
scatter_main_k(const float* __restrict__ x,
               const float4* __restrict__ yb4,
               float4* __restrict__ out4) {
    __shared__ float xs[Cc * 257];   // 257-float row stride: odd -> conflict-free

    int bid = blockIdx.x;
    int a   = g_map[bid];

    int xb = bid & 31;
    int yb = (bid >> 5) & 31;
    int n  = bid >> 10;
    int t  = threadIdx.x;

    int rowbase0 = (n * Hh * Ww + (yb << 4) * Ww + (xb << 4)) * (Cc / 4);
    const int rs4 = Ww * (Cc / 4);   // 4096 float4 per output row

    if (a < 0) {
        // pass-through copy, fully coalesced float4, loads front-batched
        float4 v[8];
        int    o[8];
        #pragma unroll
        for (int k = 0; k < 8; k++) {
            int p   = (k << 8) + t;
            int i   = p >> 7;
            int rem = p & 127;
            o[k] = rowbase0 + i * rs4 + rem;
            v[k] = __ldcs(&yb4[o[k]]);
        }
        #pragma unroll
        for (int k = 0; k < 8; k++) __stcs(&out4[o[k]], v[k]);
    } else {
        // Stage x block through SMEM (transpose): x[a][ch][pos] with
        // pos = i*16+j. Load: f = m*256 + t -> ch=m, pos=t, coalesced 128B
        // per warp; STS bank = (m + t) % 32 -> conflict-free.
        const float* xblk = x + (long)a * (Cc * 256);
        #pragma unroll
        for (int m = 0; m < Cc; m++)
            xs[m * 257 + t] = __ldcs(&xblk[m * 256 + t]);
        __syncthreads();

        // Read transposed: banks (ch+c+pos) % 32 cover all 32 banks per warp.
        #pragma unroll
        for (int k = 0; k < 8; k++) {
            int p   = (k << 8) + t;
            int i   = p >> 7;
            int rem = p & 127;
            int j   = rem >> 3;
            int ch  = (rem & 7) << 2;
            int pos = (i << 4) + j;
            float4 v;
            v.x = xs[(ch + 0) * 257 + pos];
            v.y = xs[(ch + 1) * 257 + pos];
            v.z = xs[(ch + 2) * 257 + pos];
            v.w = xs[(ch + 3) * 257 + pos];
            __stcs(&out4[rowbase0 + i * rs4 + rem], v);
        }
    }
}

extern "C" void kernel_launch(void* const* d_in, const int* in_sizes, int n_in,
                              void* d_out, int out_size) {
    const float* x      = nullptr;
    const float* y_base = nullptr;
    const int*   idx    = nullptr;

    for (int i = 0; i < n_in; i++) {
        if (in_sizes[i] == 33554432)      x      = (const float*)d_in[i];
        else if (in_sizes[i] == 67108864) y_base = (const float*)d_in[i];
        else if (in_sizes[i] == 12288)    idx    = (const int*)d_in[i];
    }

    build_map_k<<<1, 1024>>>(idx);
    scatter_main_k<<<NBLK, 256>>>(x, (const float4*)y_base, (float4*)d_out);
}